// round 1
// baseline (speedup 1.0000x reference)
#include <cuda_runtime.h>
#include <cstddef>

#define N_NODES 100000
#define N_EDGES 1600000
#define HDIM 128
#define CDIM 40

// Scratch (device globals: allocation-free rule)
__device__ float g_norm_out[N_NODES];
__device__ float g_norm_in[N_NODES];
__device__ float g_buf0[(size_t)N_NODES * HDIM];
__device__ float g_buf1[(size_t)N_NODES * HDIM];

// ---------------------------------------------------------------------------
// degrees via float atomics (counts are small integers -> exact)
__global__ void deg_kernel(const int* __restrict__ src, const int* __restrict__ dst) {
    int e = blockIdx.x * blockDim.x + threadIdx.x;
    if (e < N_EDGES) {
        atomicAdd(&g_norm_out[src[e]], 1.0f);
        atomicAdd(&g_norm_in[dst[e]], 1.0f);
    }
}

__global__ void norm_kernel() {
    int i = blockIdx.x * blockDim.x + threadIdx.x;
    if (i < N_NODES) {
        g_norm_out[i] = rsqrtf(fmaxf(g_norm_out[i], 1.0f));
        g_norm_in[i]  = rsqrtf(fmaxf(g_norm_in[i],  1.0f));
    }
}

// ---------------------------------------------------------------------------
// GEMM: out[n, 0:128] = f(in[n, :]) @ W   (W row-major [128 in, 128 out])
// MODE 0: f(v)_j = v_j * norm_out[n]                      (layer-1 pre-scale)
// MODE 1: f(v)_j = relu(v_j*norm_in[n] + bpre_j)*norm_out[n]  (post-agg of L1
//                                                          fused with L2 pre)
// Block: 256 threads, 64 nodes. X tile staged in smem with prologue applied.
// W rows read through L1 (64 KB, resident).
template <int MODE>
__global__ void __launch_bounds__(256)
gemm128_kernel(const float* __restrict__ in, const float* __restrict__ W,
               const float* __restrict__ bpre, float* __restrict__ out) {
    __shared__ float Xs[64][HDIM + 4];

    const int tid = threadIdx.x;
    const int block_row = blockIdx.x * 64;

    // stage X tile (64 x 128) with fused prologue
#pragma unroll
    for (int t = 0; t < 8; t++) {
        int idx = tid + t * 256;      // float4 index 0..2047
        int r   = idx >> 5;           // 0..63
        int c4  = (idx & 31) << 2;    // 0,4,...,124
        int n   = block_row + r;
        float4 v = make_float4(0.f, 0.f, 0.f, 0.f);
        if (n < N_NODES) {
            v = *(const float4*)(in + (size_t)n * HDIM + c4);
            if (MODE == 0) {
                float s = g_norm_out[n];
                v.x *= s; v.y *= s; v.z *= s; v.w *= s;
            } else {
                float ni = g_norm_in[n];
                float no = g_norm_out[n];
                v.x = fmaxf(fmaf(v.x, ni, bpre[c4 + 0]), 0.f) * no;
                v.y = fmaxf(fmaf(v.y, ni, bpre[c4 + 1]), 0.f) * no;
                v.z = fmaxf(fmaf(v.z, ni, bpre[c4 + 2]), 0.f) * no;
                v.w = fmaxf(fmaf(v.w, ni, bpre[c4 + 3]), 0.f) * no;
            }
        }
        *(float4*)&Xs[r][c4] = v;
    }
    __syncthreads();

    const int tx = tid & 15;   // 16 col groups x 8 cols
    const int ty = tid >> 4;   // 16 node groups x 4 nodes

    float acc[4][8];
#pragma unroll
    for (int i = 0; i < 4; i++)
#pragma unroll
        for (int j = 0; j < 8; j++) acc[i][j] = 0.f;

#pragma unroll 8
    for (int k = 0; k < HDIM; k++) {
        float4 w0 = __ldg((const float4*)(W + (size_t)k * HDIM + tx * 8));
        float4 w1 = __ldg((const float4*)(W + (size_t)k * HDIM + tx * 8 + 4));
        float xv[4];
#pragma unroll
        for (int i = 0; i < 4; i++) xv[i] = Xs[ty * 4 + i][k];
#pragma unroll
        for (int i = 0; i < 4; i++) {
            acc[i][0] = fmaf(xv[i], w0.x, acc[i][0]);
            acc[i][1] = fmaf(xv[i], w0.y, acc[i][1]);
            acc[i][2] = fmaf(xv[i], w0.z, acc[i][2]);
            acc[i][3] = fmaf(xv[i], w0.w, acc[i][3]);
            acc[i][4] = fmaf(xv[i], w1.x, acc[i][4]);
            acc[i][5] = fmaf(xv[i], w1.y, acc[i][5]);
            acc[i][6] = fmaf(xv[i], w1.z, acc[i][6]);
            acc[i][7] = fmaf(xv[i], w1.w, acc[i][7]);
        }
    }

#pragma unroll
    for (int i = 0; i < 4; i++) {
        int n = block_row + ty * 4 + i;
        if (n < N_NODES) {
            float* p = out + (size_t)n * HDIM + tx * 8;
            *(float4*)(p)     = make_float4(acc[i][0], acc[i][1], acc[i][2], acc[i][3]);
            *(float4*)(p + 4) = make_float4(acc[i][4], acc[i][5], acc[i][6], acc[i][7]);
        }
    }
}

// ---------------------------------------------------------------------------
// scatter-add: hout[dst[e], :] += hin[src[e], :]   warp per edge, float4/lane
__global__ void __launch_bounds__(256)
scatter_kernel(const int* __restrict__ src, const int* __restrict__ dst,
               const float* __restrict__ hin, float* __restrict__ hout) {
    int t    = blockIdx.x * blockDim.x + threadIdx.x;
    int e    = t >> 5;
    int lane = t & 31;
    if (e >= N_EDGES) return;
    int s = src[e];
    int d = dst[e];
    float4 v = __ldg((const float4*)hin + (size_t)s * 32 + lane);
    float4* p = (float4*)hout + (size_t)d * 32 + lane;
    asm volatile("red.global.add.v4.f32 [%0], {%1, %2, %3, %4};"
                 :: "l"(p), "f"(v.x), "f"(v.y), "f"(v.z), "f"(v.w)
                 : "memory");
}

// ---------------------------------------------------------------------------
// Final FC: out[n, c] = sum_j (agg[n,j]*norm_in[n] + b2[j]) * Wfc[j,c] + bfc[c]
// Block: 256 threads, 32 nodes; Wfc (20 KB) + X tile (17 KB) in smem.
__global__ void __launch_bounds__(256)
fc_kernel(const float* __restrict__ agg, const float* __restrict__ b2,
          const float* __restrict__ Wfc, const float* __restrict__ bfc,
          float* __restrict__ out) {
    __shared__ float Xs[32][HDIM + 4];
    __shared__ float Ws[HDIM * CDIM];

    const int tid = threadIdx.x;
    const int block_row = blockIdx.x * 32;

    for (int i = tid; i < HDIM * CDIM; i += 256) Ws[i] = Wfc[i];

#pragma unroll
    for (int t = 0; t < 4; t++) {
        int idx = tid + t * 256;      // float4 index 0..1023
        int r   = idx >> 5;           // 0..31
        int c4  = (idx & 31) << 2;
        int n   = block_row + r;
        float4 v = make_float4(0.f, 0.f, 0.f, 0.f);
        if (n < N_NODES) {
            v = *(const float4*)(agg + (size_t)n * HDIM + c4);
            float ni = g_norm_in[n];
            v.x = fmaf(v.x, ni, b2[c4 + 0]);
            v.y = fmaf(v.y, ni, b2[c4 + 1]);
            v.z = fmaf(v.z, ni, b2[c4 + 2]);
            v.w = fmaf(v.w, ni, b2[c4 + 3]);
        }
        *(float4*)&Xs[r][c4] = v;
    }
    __syncthreads();

    const int tx = tid & 7;    // 8 col groups x 5 cols = 40
    const int ty = tid >> 3;   // 32 nodes

    float acc[5] = {0.f, 0.f, 0.f, 0.f, 0.f};
#pragma unroll 8
    for (int k = 0; k < HDIM; k++) {
        float xv = Xs[ty][k];
#pragma unroll
        for (int j = 0; j < 5; j++)
            acc[j] = fmaf(xv, Ws[k * CDIM + tx * 5 + j], acc[j]);
    }

    int n = block_row + ty;
    if (n < N_NODES) {
#pragma unroll
        for (int j = 0; j < 5; j++)
            out[(size_t)n * CDIM + tx * 5 + j] = acc[j] + bfc[tx * 5 + j];
    }
}

// ---------------------------------------------------------------------------
extern "C" void kernel_launch(void* const* d_in, const int* in_sizes, int n_in,
                              void* d_out, int out_size) {
    const float* x   = (const float*)d_in[0];
    const int*   ei  = (const int*)  d_in[1];
    const float* W1  = (const float*)d_in[2];
    const float* b1  = (const float*)d_in[3];
    const float* W2  = (const float*)d_in[4];
    const float* b2  = (const float*)d_in[5];
    const float* Wfc = (const float*)d_in[6];
    const float* bfc = (const float*)d_in[7];
    float* out = (float*)d_out;

    const int* src = ei;            // edge_index row 0
    const int* dst = ei + N_EDGES;  // edge_index row 1

    float *p_no, *p_ni, *p_b0, *p_b1;
    cudaGetSymbolAddress((void**)&p_no, g_norm_out);
    cudaGetSymbolAddress((void**)&p_ni, g_norm_in);
    cudaGetSymbolAddress((void**)&p_b0, g_buf0);
    cudaGetSymbolAddress((void**)&p_b1, g_buf1);

    const size_t feat_bytes = (size_t)N_NODES * HDIM * sizeof(float);

    // degrees -> norms
    cudaMemsetAsync(p_no, 0, N_NODES * sizeof(float));
    cudaMemsetAsync(p_ni, 0, N_NODES * sizeof(float));
    deg_kernel<<<(N_EDGES + 255) / 256, 256>>>(src, dst);
    norm_kernel<<<(N_NODES + 255) / 256, 256>>>();

    const int gemm_blocks = (N_NODES + 63) / 64;
    const int scat_blocks = (int)(((long long)N_EDGES * 32 + 255) / 256);

    // Layer 1: buf0 = (x * norm_out) @ W1 ; buf1 = scatter(buf0)
    gemm128_kernel<0><<<gemm_blocks, 256>>>(x, W1, nullptr, p_b0);
    cudaMemsetAsync(p_b1, 0, feat_bytes);
    scatter_kernel<<<scat_blocks, 256>>>(src, dst, p_b0, p_b1);

    // Layer 2: buf0 = relu(buf1*norm_in + b1)*norm_out @ W2 ; buf1 = scatter
    gemm128_kernel<1><<<gemm_blocks, 256>>>(p_b1, W2, b1, p_b0);
    cudaMemsetAsync(p_b1, 0, feat_bytes);
    scatter_kernel<<<scat_blocks, 256>>>(src, dst, p_b0, p_b1);

    // FC: out = (buf1*norm_in + b2) @ Wfc + bfc
    fc_kernel<<<(N_NODES + 31) / 32, 256>>>(p_b1, b2, Wfc, bfc, out);
}

// round 2
// speedup vs baseline: 1.0291x; 1.0291x over previous
#include <cuda_runtime.h>
#include <cstddef>

#define N_NODES 100000
#define N_EDGES 1600000
#define HDIM 128
#define CDIM 40

#define SCAN_T 1024
#define SCAN_BLOCKS ((N_NODES + SCAN_T - 1) / SCAN_T)   // 98

// Scratch (device globals: allocation-free rule)
__device__ float g_norm_out[N_NODES];
__device__ float g_norm_in[N_NODES];
__device__ int   g_deg_out[N_NODES];
__device__ int   g_deg_in[N_NODES];
__device__ int   g_off[N_NODES + 1];
__device__ int   g_cursor[N_NODES];
__device__ int   g_csr_src[N_EDGES];
__device__ int   g_bsum[SCAN_BLOCKS];
__device__ int   g_boff[SCAN_BLOCKS];
__device__ float g_buf0[(size_t)N_NODES * HDIM];
__device__ float g_buf1[(size_t)N_NODES * HDIM];

// ---------------------------------------------------------------------------
// integer degree histogram (also feeds CSR offsets)
__global__ void deg_kernel(const int* __restrict__ src, const int* __restrict__ dst) {
    int e = blockIdx.x * blockDim.x + threadIdx.x;
    if (e < N_EDGES) {
        atomicAdd(&g_deg_out[src[e]], 1);
        atomicAdd(&g_deg_in[dst[e]], 1);
    }
}

__global__ void norm_kernel() {
    int i = blockIdx.x * blockDim.x + threadIdx.x;
    if (i < N_NODES) {
        g_norm_out[i] = rsqrtf(fmaxf((float)g_deg_out[i], 1.0f));
        g_norm_in[i]  = rsqrtf(fmaxf((float)g_deg_in[i],  1.0f));
    }
}

// ---------------------------------------------------------------------------
// 3-kernel exclusive scan of g_deg_in -> g_off (off[0]=0, off[i+1]=sum deg[0..i])
__global__ void scan1_kernel() {
    __shared__ int sm[SCAN_T];
    int i = blockIdx.x * SCAN_T + threadIdx.x;
    int v = (i < N_NODES) ? g_deg_in[i] : 0;
    sm[threadIdx.x] = v;
    __syncthreads();
    for (int ofs = 1; ofs < SCAN_T; ofs <<= 1) {
        int t = (threadIdx.x >= ofs) ? sm[threadIdx.x - ofs] : 0;
        __syncthreads();
        sm[threadIdx.x] += t;
        __syncthreads();
    }
    if (i < N_NODES) g_off[i + 1] = sm[threadIdx.x];
    if (threadIdx.x == SCAN_T - 1) g_bsum[blockIdx.x] = sm[threadIdx.x];
    if (i == 0) g_off[0] = 0;
}

__global__ void scan2_kernel() {
    __shared__ int sm[128];
    int v = (threadIdx.x < SCAN_BLOCKS) ? g_bsum[threadIdx.x] : 0;
    sm[threadIdx.x] = v;
    __syncthreads();
    for (int ofs = 1; ofs < 128; ofs <<= 1) {
        int t = (threadIdx.x >= ofs) ? sm[threadIdx.x - ofs] : 0;
        __syncthreads();
        sm[threadIdx.x] += t;
        __syncthreads();
    }
    if (threadIdx.x < SCAN_BLOCKS)
        g_boff[threadIdx.x] = (threadIdx.x == 0) ? 0 : sm[threadIdx.x - 1];
}

__global__ void scan3_kernel() {
    int i = blockIdx.x * SCAN_T + threadIdx.x;
    if (i < N_NODES) g_off[i + 1] += g_boff[blockIdx.x];
}

// CSR fill: bucket src ids by dst
__global__ void fill_csr_kernel(const int* __restrict__ src, const int* __restrict__ dst) {
    int e = blockIdx.x * blockDim.x + threadIdx.x;
    if (e < N_EDGES) {
        int d = dst[e];
        int pos = g_off[d] + atomicAdd(&g_cursor[d], 1);
        g_csr_src[pos] = src[e];
    }
}

// ---------------------------------------------------------------------------
// GEMM: out[n, 0:128] = f(in[n, :]) @ W   (W row-major [128 in, 128 out])
// MODE 0: f(v)_j = v_j * norm_out[n]
// MODE 1: f(v)_j = relu(v_j*norm_in[n] + bpre_j)*norm_out[n]
template <int MODE>
__global__ void __launch_bounds__(256)
gemm128_kernel(const float* __restrict__ in, const float* __restrict__ W,
               const float* __restrict__ bpre, float* __restrict__ out) {
    __shared__ float Xs[64][HDIM + 4];

    const int tid = threadIdx.x;
    const int block_row = blockIdx.x * 64;

#pragma unroll
    for (int t = 0; t < 8; t++) {
        int idx = tid + t * 256;
        int r   = idx >> 5;
        int c4  = (idx & 31) << 2;
        int n   = block_row + r;
        float4 v = make_float4(0.f, 0.f, 0.f, 0.f);
        if (n < N_NODES) {
            v = *(const float4*)(in + (size_t)n * HDIM + c4);
            if (MODE == 0) {
                float s = g_norm_out[n];
                v.x *= s; v.y *= s; v.z *= s; v.w *= s;
            } else {
                float ni = g_norm_in[n];
                float no = g_norm_out[n];
                v.x = fmaxf(fmaf(v.x, ni, bpre[c4 + 0]), 0.f) * no;
                v.y = fmaxf(fmaf(v.y, ni, bpre[c4 + 1]), 0.f) * no;
                v.z = fmaxf(fmaf(v.z, ni, bpre[c4 + 2]), 0.f) * no;
                v.w = fmaxf(fmaf(v.w, ni, bpre[c4 + 3]), 0.f) * no;
            }
        }
        *(float4*)&Xs[r][c4] = v;
    }
    __syncthreads();

    const int tx = tid & 15;
    const int ty = tid >> 4;

    float acc[4][8];
#pragma unroll
    for (int i = 0; i < 4; i++)
#pragma unroll
        for (int j = 0; j < 8; j++) acc[i][j] = 0.f;

#pragma unroll 8
    for (int k = 0; k < HDIM; k++) {
        float4 w0 = __ldg((const float4*)(W + (size_t)k * HDIM + tx * 8));
        float4 w1 = __ldg((const float4*)(W + (size_t)k * HDIM + tx * 8 + 4));
        float xv[4];
#pragma unroll
        for (int i = 0; i < 4; i++) xv[i] = Xs[ty * 4 + i][k];
#pragma unroll
        for (int i = 0; i < 4; i++) {
            acc[i][0] = fmaf(xv[i], w0.x, acc[i][0]);
            acc[i][1] = fmaf(xv[i], w0.y, acc[i][1]);
            acc[i][2] = fmaf(xv[i], w0.z, acc[i][2]);
            acc[i][3] = fmaf(xv[i], w0.w, acc[i][3]);
            acc[i][4] = fmaf(xv[i], w1.x, acc[i][4]);
            acc[i][5] = fmaf(xv[i], w1.y, acc[i][5]);
            acc[i][6] = fmaf(xv[i], w1.z, acc[i][6]);
            acc[i][7] = fmaf(xv[i], w1.w, acc[i][7]);
        }
    }

#pragma unroll
    for (int i = 0; i < 4; i++) {
        int n = block_row + ty * 4 + i;
        if (n < N_NODES) {
            float* p = out + (size_t)n * HDIM + tx * 8;
            *(float4*)(p)     = make_float4(acc[i][0], acc[i][1], acc[i][2], acc[i][3]);
            *(float4*)(p + 4) = make_float4(acc[i][4], acc[i][5], acc[i][6], acc[i][7]);
        }
    }
}

// ---------------------------------------------------------------------------
// CSR gather-aggregate: hout[n, :] = sum_{e in in-edges(n)} hin[csr_src[e], :]
// warp per node, float4 per lane, 4-way src pipelining for MLP.
__global__ void __launch_bounds__(256)
gather_agg_kernel(const float* __restrict__ hin, float* __restrict__ hout) {
    int t    = blockIdx.x * blockDim.x + threadIdx.x;
    int node = t >> 5;
    int lane = t & 31;
    if (node >= N_NODES) return;

    int beg = g_off[node];
    int end = g_off[node + 1];

    const float4* in4 = (const float4*)hin;
    float4 acc = make_float4(0.f, 0.f, 0.f, 0.f);

    int i = beg;
    for (; i + 4 <= end; i += 4) {
        int s0 = g_csr_src[i + 0];
        int s1 = g_csr_src[i + 1];
        int s2 = g_csr_src[i + 2];
        int s3 = g_csr_src[i + 3];
        float4 v0 = __ldg(in4 + (size_t)s0 * 32 + lane);
        float4 v1 = __ldg(in4 + (size_t)s1 * 32 + lane);
        float4 v2 = __ldg(in4 + (size_t)s2 * 32 + lane);
        float4 v3 = __ldg(in4 + (size_t)s3 * 32 + lane);
        acc.x += (v0.x + v1.x) + (v2.x + v3.x);
        acc.y += (v0.y + v1.y) + (v2.y + v3.y);
        acc.z += (v0.z + v1.z) + (v2.z + v3.z);
        acc.w += (v0.w + v1.w) + (v2.w + v3.w);
    }
    for (; i < end; i++) {
        int s = g_csr_src[i];
        float4 v = __ldg(in4 + (size_t)s * 32 + lane);
        acc.x += v.x; acc.y += v.y; acc.z += v.z; acc.w += v.w;
    }

    ((float4*)hout)[(size_t)node * 32 + lane] = acc;
}

// ---------------------------------------------------------------------------
// Final FC: out[n, c] = sum_j (agg[n,j]*norm_in[n] + b2[j]) * Wfc[j,c] + bfc[c]
__global__ void __launch_bounds__(256)
fc_kernel(const float* __restrict__ agg, const float* __restrict__ b2,
          const float* __restrict__ Wfc, const float* __restrict__ bfc,
          float* __restrict__ out) {
    __shared__ float Xs[32][HDIM + 4];
    __shared__ float Ws[HDIM * CDIM];

    const int tid = threadIdx.x;
    const int block_row = blockIdx.x * 32;

    for (int i = tid; i < HDIM * CDIM; i += 256) Ws[i] = Wfc[i];

#pragma unroll
    for (int t = 0; t < 4; t++) {
        int idx = tid + t * 256;
        int r   = idx >> 5;
        int c4  = (idx & 31) << 2;
        int n   = block_row + r;
        float4 v = make_float4(0.f, 0.f, 0.f, 0.f);
        if (n < N_NODES) {
            v = *(const float4*)(agg + (size_t)n * HDIM + c4);
            float ni = g_norm_in[n];
            v.x = fmaf(v.x, ni, b2[c4 + 0]);
            v.y = fmaf(v.y, ni, b2[c4 + 1]);
            v.z = fmaf(v.z, ni, b2[c4 + 2]);
            v.w = fmaf(v.w, ni, b2[c4 + 3]);
        }
        *(float4*)&Xs[r][c4] = v;
    }
    __syncthreads();

    const int tx = tid & 7;
    const int ty = tid >> 3;

    float acc[5] = {0.f, 0.f, 0.f, 0.f, 0.f};
#pragma unroll 8
    for (int k = 0; k < HDIM; k++) {
        float xv = Xs[ty][k];
#pragma unroll
        for (int j = 0; j < 5; j++)
            acc[j] = fmaf(xv, Ws[k * CDIM + tx * 5 + j], acc[j]);
    }

    int n = block_row + ty;
    if (n < N_NODES) {
#pragma unroll
        for (int j = 0; j < 5; j++)
            out[(size_t)n * CDIM + tx * 5 + j] = acc[j] + bfc[tx * 5 + j];
    }
}

// ---------------------------------------------------------------------------
extern "C" void kernel_launch(void* const* d_in, const int* in_sizes, int n_in,
                              void* d_out, int out_size) {
    const float* x   = (const float*)d_in[0];
    const int*   ei  = (const int*)  d_in[1];
    const float* W1  = (const float*)d_in[2];
    const float* b1  = (const float*)d_in[3];
    const float* W2  = (const float*)d_in[4];
    const float* b2  = (const float*)d_in[5];
    const float* Wfc = (const float*)d_in[6];
    const float* bfc = (const float*)d_in[7];
    float* out = (float*)d_out;

    const int* src = ei;            // edge_index row 0
    const int* dst = ei + N_EDGES;  // edge_index row 1

    float *p_b0, *p_b1;
    int *p_do, *p_di, *p_cur;
    cudaGetSymbolAddress((void**)&p_b0,  g_buf0);
    cudaGetSymbolAddress((void**)&p_b1,  g_buf1);
    cudaGetSymbolAddress((void**)&p_do,  g_deg_out);
    cudaGetSymbolAddress((void**)&p_di,  g_deg_in);
    cudaGetSymbolAddress((void**)&p_cur, g_cursor);

    // ---- CSR + norms build ----
    cudaMemsetAsync(p_do,  0, N_NODES * sizeof(int));
    cudaMemsetAsync(p_di,  0, N_NODES * sizeof(int));
    cudaMemsetAsync(p_cur, 0, N_NODES * sizeof(int));
    deg_kernel<<<(N_EDGES + 255) / 256, 256>>>(src, dst);
    norm_kernel<<<(N_NODES + 255) / 256, 256>>>();
    scan1_kernel<<<SCAN_BLOCKS, SCAN_T>>>();
    scan2_kernel<<<1, 128>>>();
    scan3_kernel<<<SCAN_BLOCKS, SCAN_T>>>();
    fill_csr_kernel<<<(N_EDGES + 255) / 256, 256>>>(src, dst);

    const int gemm_blocks = (N_NODES + 63) / 64;
    const int agg_blocks  = (int)(((long long)N_NODES * 32 + 255) / 256);

    // Layer 1: buf0 = (x * norm_out) @ W1 ; buf1 = gather_agg(buf0)
    gemm128_kernel<0><<<gemm_blocks, 256>>>(x, W1, nullptr, p_b0);
    gather_agg_kernel<<<agg_blocks, 256>>>(p_b0, p_b1);

    // Layer 2: buf0 = relu(buf1*norm_in + b1)*norm_out @ W2 ; buf1 = gather_agg
    gemm128_kernel<1><<<gemm_blocks, 256>>>(p_b1, W2, b1, p_b0);
    gather_agg_kernel<<<agg_blocks, 256>>>(p_b0, p_b1);

    // FC: out = (buf1*norm_in + b2) @ Wfc + bfc
    fc_kernel<<<(N_NODES + 31) / 32, 256>>>(p_b1, b2, Wfc, bfc, out);
}

// round 3
// speedup vs baseline: 1.9970x; 1.9405x over previous
#include <cuda_runtime.h>
#include <cstddef>

#define N_NODES 100000
#define N_EDGES 1600000
#define HDIM 128
#define CDIM 40

#define SCAN_T 1024
#define SCAN_BLOCKS ((N_NODES + SCAN_T - 1) / SCAN_T)   // 98

// Scratch (device globals: allocation-free rule)
__device__ float g_norm_out[N_NODES];
__device__ float g_norm_in[N_NODES];
__device__ int   g_deg_out[N_NODES];
__device__ int   g_deg_in[N_NODES];
__device__ int   g_off[N_NODES + 1];
__device__ int   g_cursor[N_NODES];
__device__ int   g_csr_src[N_EDGES];
__device__ int   g_bsum[SCAN_BLOCKS];
__device__ int   g_boff[SCAN_BLOCKS];
__device__ float g_wcomb[HDIM * CDIM];
__device__ float g_bcomb[CDIM];
__device__ float g_buf0[(size_t)N_NODES * HDIM];
__device__ float g_buf1[(size_t)N_NODES * HDIM];

// ---------------------------------------------------------------------------
// integer degree histogram (also feeds CSR offsets)
__global__ void deg_kernel(const int* __restrict__ src, const int* __restrict__ dst) {
    int e = blockIdx.x * blockDim.x + threadIdx.x;
    if (e < N_EDGES) {
        atomicAdd(&g_deg_out[src[e]], 1);
        atomicAdd(&g_deg_in[dst[e]], 1);
    }
}

__global__ void norm_kernel() {
    int i = blockIdx.x * blockDim.x + threadIdx.x;
    if (i < N_NODES) {
        g_norm_out[i] = rsqrtf(fmaxf((float)g_deg_out[i], 1.0f));
        g_norm_in[i]  = rsqrtf(fmaxf((float)g_deg_in[i],  1.0f));
    }
}

// ---------------------------------------------------------------------------
// 3-kernel exclusive scan of g_deg_in -> g_off
__global__ void scan1_kernel() {
    __shared__ int sm[SCAN_T];
    int i = blockIdx.x * SCAN_T + threadIdx.x;
    int v = (i < N_NODES) ? g_deg_in[i] : 0;
    sm[threadIdx.x] = v;
    __syncthreads();
    for (int ofs = 1; ofs < SCAN_T; ofs <<= 1) {
        int t = (threadIdx.x >= ofs) ? sm[threadIdx.x - ofs] : 0;
        __syncthreads();
        sm[threadIdx.x] += t;
        __syncthreads();
    }
    if (i < N_NODES) g_off[i + 1] = sm[threadIdx.x];
    if (threadIdx.x == SCAN_T - 1) g_bsum[blockIdx.x] = sm[threadIdx.x];
    if (i == 0) g_off[0] = 0;
}

__global__ void scan2_kernel() {
    __shared__ int sm[128];
    int v = (threadIdx.x < SCAN_BLOCKS) ? g_bsum[threadIdx.x] : 0;
    sm[threadIdx.x] = v;
    __syncthreads();
    for (int ofs = 1; ofs < 128; ofs <<= 1) {
        int t = (threadIdx.x >= ofs) ? sm[threadIdx.x - ofs] : 0;
        __syncthreads();
        sm[threadIdx.x] += t;
        __syncthreads();
    }
    if (threadIdx.x < SCAN_BLOCKS)
        g_boff[threadIdx.x] = (threadIdx.x == 0) ? 0 : sm[threadIdx.x - 1];
}

__global__ void scan3_kernel() {
    int i = blockIdx.x * SCAN_T + threadIdx.x;
    if (i < N_NODES) g_off[i + 1] += g_boff[blockIdx.x];
}

// CSR fill: bucket src ids by dst
__global__ void fill_csr_kernel(const int* __restrict__ src, const int* __restrict__ dst) {
    int e = blockIdx.x * blockDim.x + threadIdx.x;
    if (e < N_EDGES) {
        int d = dst[e];
        int pos = g_off[d] + atomicAdd(&g_cursor[d], 1);
        g_csr_src[pos] = src[e];
    }
}

// ---------------------------------------------------------------------------
// Fold layer-2 weight through the FC: Wcomb = W2 @ Wfc, bcomb = b2 @ Wfc + bfc
// grid = HDIM blocks (row j of W2), 64 threads covering CDIM cols.
__global__ void wcomb_kernel(const float* __restrict__ W2, const float* __restrict__ Wfc) {
    __shared__ float w2row[HDIM];
    int j = blockIdx.x;
    for (int k = threadIdx.x; k < HDIM; k += blockDim.x) w2row[k] = W2[j * HDIM + k];
    __syncthreads();
    int c = threadIdx.x;
    if (c < CDIM) {
        float acc = 0.f;
#pragma unroll 8
        for (int k = 0; k < HDIM; k++)
            acc = fmaf(w2row[k], Wfc[k * CDIM + c], acc);
        g_wcomb[j * CDIM + c] = acc;
    }
}

__global__ void bcomb_kernel(const float* __restrict__ b2, const float* __restrict__ Wfc,
                             const float* __restrict__ bfc) {
    int c = threadIdx.x;
    if (c < CDIM) {
        float acc = bfc[c];
        for (int k = 0; k < HDIM; k++)
            acc = fmaf(b2[k], Wfc[k * CDIM + c], acc);
        g_bcomb[c] = acc;
    }
}

// ---------------------------------------------------------------------------
// CSR gather-aggregate: hout[n, :] = sum_{s in N_in(n)} hin[s, :] * (SCALE ? norm_out[s] : 1)
// warp per node, float4 per lane, 4-way src pipelining for MLP.
template <int SCALE>
__global__ void __launch_bounds__(256)
gather_agg_kernel(const float* __restrict__ hin, float* __restrict__ hout) {
    int t    = blockIdx.x * blockDim.x + threadIdx.x;
    int node = t >> 5;
    int lane = t & 31;
    if (node >= N_NODES) return;

    int beg = g_off[node];
    int end = g_off[node + 1];

    const float4* in4 = (const float4*)hin;
    float4 acc = make_float4(0.f, 0.f, 0.f, 0.f);

    int i = beg;
    for (; i + 4 <= end; i += 4) {
        int s0 = g_csr_src[i + 0];
        int s1 = g_csr_src[i + 1];
        int s2 = g_csr_src[i + 2];
        int s3 = g_csr_src[i + 3];
        float n0 = 1.f, n1 = 1.f, n2 = 1.f, n3 = 1.f;
        if (SCALE) { n0 = g_norm_out[s0]; n1 = g_norm_out[s1];
                     n2 = g_norm_out[s2]; n3 = g_norm_out[s3]; }
        float4 v0 = __ldg(in4 + (size_t)s0 * 32 + lane);
        float4 v1 = __ldg(in4 + (size_t)s1 * 32 + lane);
        float4 v2 = __ldg(in4 + (size_t)s2 * 32 + lane);
        float4 v3 = __ldg(in4 + (size_t)s3 * 32 + lane);
        if (SCALE) {
            acc.x = fmaf(v0.x, n0, fmaf(v1.x, n1, fmaf(v2.x, n2, fmaf(v3.x, n3, acc.x))));
            acc.y = fmaf(v0.y, n0, fmaf(v1.y, n1, fmaf(v2.y, n2, fmaf(v3.y, n3, acc.y))));
            acc.z = fmaf(v0.z, n0, fmaf(v1.z, n1, fmaf(v2.z, n2, fmaf(v3.z, n3, acc.z))));
            acc.w = fmaf(v0.w, n0, fmaf(v1.w, n1, fmaf(v2.w, n2, fmaf(v3.w, n3, acc.w))));
        } else {
            acc.x += (v0.x + v1.x) + (v2.x + v3.x);
            acc.y += (v0.y + v1.y) + (v2.y + v3.y);
            acc.z += (v0.z + v1.z) + (v2.z + v3.z);
            acc.w += (v0.w + v1.w) + (v2.w + v3.w);
        }
    }
    for (; i < end; i++) {
        int s = g_csr_src[i];
        float ns = SCALE ? g_norm_out[s] : 1.f;
        float4 v = __ldg(in4 + (size_t)s * 32 + lane);
        acc.x = fmaf(v.x, ns, acc.x); acc.y = fmaf(v.y, ns, acc.y);
        acc.z = fmaf(v.z, ns, acc.z); acc.w = fmaf(v.w, ns, acc.w);
    }

    ((float4*)hout)[(size_t)node * 32 + lane] = acc;
}

// ---------------------------------------------------------------------------
// Layer-1 GEMM: out[n,:] = relu((in[n,:]*norm_in[n]) @ W1 + b1) * norm_out[n]
__global__ void __launch_bounds__(256)
gemm_l1_kernel(const float* __restrict__ in, const float* __restrict__ W,
               const float* __restrict__ bias, float* __restrict__ out) {
    __shared__ float Xs[64][HDIM + 4];

    const int tid = threadIdx.x;
    const int block_row = blockIdx.x * 64;

#pragma unroll
    for (int t = 0; t < 8; t++) {
        int idx = tid + t * 256;
        int r   = idx >> 5;
        int c4  = (idx & 31) << 2;
        int n   = block_row + r;
        float4 v = make_float4(0.f, 0.f, 0.f, 0.f);
        if (n < N_NODES) {
            v = *(const float4*)(in + (size_t)n * HDIM + c4);
            float s = g_norm_in[n];
            v.x *= s; v.y *= s; v.z *= s; v.w *= s;
        }
        *(float4*)&Xs[r][c4] = v;
    }
    __syncthreads();

    const int tx = tid & 15;   // 16 col groups x 8 cols
    const int ty = tid >> 4;   // 16 node groups x 4 nodes

    float acc[4][8];
#pragma unroll
    for (int i = 0; i < 4; i++)
#pragma unroll
        for (int j = 0; j < 8; j++) acc[i][j] = 0.f;

#pragma unroll 8
    for (int k = 0; k < HDIM; k++) {
        float4 w0 = __ldg((const float4*)(W + (size_t)k * HDIM + tx * 8));
        float4 w1 = __ldg((const float4*)(W + (size_t)k * HDIM + tx * 8 + 4));
        float xv[4];
#pragma unroll
        for (int i = 0; i < 4; i++) xv[i] = Xs[ty * 4 + i][k];
#pragma unroll
        for (int i = 0; i < 4; i++) {
            acc[i][0] = fmaf(xv[i], w0.x, acc[i][0]);
            acc[i][1] = fmaf(xv[i], w0.y, acc[i][1]);
            acc[i][2] = fmaf(xv[i], w0.z, acc[i][2]);
            acc[i][3] = fmaf(xv[i], w0.w, acc[i][3]);
            acc[i][4] = fmaf(xv[i], w1.x, acc[i][4]);
            acc[i][5] = fmaf(xv[i], w1.y, acc[i][5]);
            acc[i][6] = fmaf(xv[i], w1.z, acc[i][6]);
            acc[i][7] = fmaf(xv[i], w1.w, acc[i][7]);
        }
    }

    float4 bv0 = __ldg((const float4*)(bias + tx * 8));
    float4 bv1 = __ldg((const float4*)(bias + tx * 8 + 4));

#pragma unroll
    for (int i = 0; i < 4; i++) {
        int n = block_row + ty * 4 + i;
        if (n < N_NODES) {
            float no = g_norm_out[n];
            float r0 = fmaxf(acc[i][0] + bv0.x, 0.f) * no;
            float r1 = fmaxf(acc[i][1] + bv0.y, 0.f) * no;
            float r2 = fmaxf(acc[i][2] + bv0.z, 0.f) * no;
            float r3 = fmaxf(acc[i][3] + bv0.w, 0.f) * no;
            float r4 = fmaxf(acc[i][4] + bv1.x, 0.f) * no;
            float r5 = fmaxf(acc[i][5] + bv1.y, 0.f) * no;
            float r6 = fmaxf(acc[i][6] + bv1.z, 0.f) * no;
            float r7 = fmaxf(acc[i][7] + bv1.w, 0.f) * no;
            float* p = out + (size_t)n * HDIM + tx * 8;
            *(float4*)(p)     = make_float4(r0, r1, r2, r3);
            *(float4*)(p + 4) = make_float4(r4, r5, r6, r7);
        }
    }
}

// ---------------------------------------------------------------------------
// Final fused FC: out[n, c] = (agg[n,:]*norm_in[n]) @ Wcomb[:,c] + bcomb[c]
__global__ void __launch_bounds__(256)
fc_kernel(const float* __restrict__ agg, float* __restrict__ out) {
    __shared__ float Xs[32][HDIM + 4];
    __shared__ float Ws[HDIM * CDIM];

    const int tid = threadIdx.x;
    const int block_row = blockIdx.x * 32;

    for (int i = tid; i < HDIM * CDIM; i += 256) Ws[i] = g_wcomb[i];

#pragma unroll
    for (int t = 0; t < 4; t++) {
        int idx = tid + t * 256;
        int r   = idx >> 5;
        int c4  = (idx & 31) << 2;
        int n   = block_row + r;
        float4 v = make_float4(0.f, 0.f, 0.f, 0.f);
        if (n < N_NODES) {
            v = *(const float4*)(agg + (size_t)n * HDIM + c4);
            float ni = g_norm_in[n];
            v.x *= ni; v.y *= ni; v.z *= ni; v.w *= ni;
        }
        *(float4*)&Xs[r][c4] = v;
    }
    __syncthreads();

    const int tx = tid & 7;    // 8 col groups x 5 cols = 40
    const int ty = tid >> 3;   // 32 nodes

    float acc[5] = {0.f, 0.f, 0.f, 0.f, 0.f};
#pragma unroll 8
    for (int k = 0; k < HDIM; k++) {
        float xv = Xs[ty][k];
#pragma unroll
        for (int j = 0; j < 5; j++)
            acc[j] = fmaf(xv, Ws[k * CDIM + tx * 5 + j], acc[j]);
    }

    int n = block_row + ty;
    if (n < N_NODES) {
#pragma unroll
        for (int j = 0; j < 5; j++)
            out[(size_t)n * CDIM + tx * 5 + j] = acc[j] + g_bcomb[tx * 5 + j];
    }
}

// ---------------------------------------------------------------------------
extern "C" void kernel_launch(void* const* d_in, const int* in_sizes, int n_in,
                              void* d_out, int out_size) {
    const float* x   = (const float*)d_in[0];
    const int*   ei  = (const int*)  d_in[1];
    const float* W1  = (const float*)d_in[2];
    const float* b1  = (const float*)d_in[3];
    const float* W2  = (const float*)d_in[4];
    const float* b2  = (const float*)d_in[5];
    const float* Wfc = (const float*)d_in[6];
    const float* bfc = (const float*)d_in[7];
    float* out = (float*)d_out;

    const int* src = ei;            // edge_index row 0
    const int* dst = ei + N_EDGES;  // edge_index row 1

    float *p_b0, *p_b1;
    int *p_do, *p_di, *p_cur;
    cudaGetSymbolAddress((void**)&p_b0,  g_buf0);
    cudaGetSymbolAddress((void**)&p_b1,  g_buf1);
    cudaGetSymbolAddress((void**)&p_do,  g_deg_out);
    cudaGetSymbolAddress((void**)&p_di,  g_deg_in);
    cudaGetSymbolAddress((void**)&p_cur, g_cursor);

    // ---- CSR + norms + folded-weight build ----
    cudaMemsetAsync(p_do,  0, N_NODES * sizeof(int));
    cudaMemsetAsync(p_di,  0, N_NODES * sizeof(int));
    cudaMemsetAsync(p_cur, 0, N_NODES * sizeof(int));
    deg_kernel<<<(N_EDGES + 255) / 256, 256>>>(src, dst);
    norm_kernel<<<(N_NODES + 255) / 256, 256>>>();
    scan1_kernel<<<SCAN_BLOCKS, SCAN_T>>>();
    scan2_kernel<<<1, 128>>>();
    scan3_kernel<<<SCAN_BLOCKS, SCAN_T>>>();
    fill_csr_kernel<<<(N_EDGES + 255) / 256, 256>>>(src, dst);
    wcomb_kernel<<<HDIM, 64>>>(W2, Wfc);
    bcomb_kernel<<<1, 64>>>(b2, Wfc, bfc);

    const int gemm_blocks = (N_NODES + 63) / 64;
    const int agg_blocks  = (int)(((long long)N_NODES * 32 + 255) / 256);

    // a1 = gather(x * norm_out[src])          -> buf0
    gather_agg_kernel<1><<<agg_blocks, 256>>>(x, p_b0);
    // r  = relu((a1*norm_in)@W1 + b1)*norm_out -> buf1
    gemm_l1_kernel<<<gemm_blocks, 256>>>(p_b0, W1, b1, p_b1);
    // a2 = gather(r)                           -> buf0
    gather_agg_kernel<0><<<agg_blocks, 256>>>(p_b1, p_b0);
    // out = (a2*norm_in)@Wcomb + bcomb
    fc_kernel<<<(N_NODES + 31) / 32, 256>>>(p_b0, out);
}